// round 6
// baseline (speedup 1.0000x reference)
#include <cuda_runtime.h>
#include <math.h>

#define TT 2048
#define BB 64
#define DD 256
#define HH 512

#define GC 16          // CTAs per group
#define NGRP 16        // 16 groups x 4 batch (each CTA serves 2 groups: streams A,B)
#define JC 32          // output columns owned per CTA
#define NT 256

// ---------------- packed fp32x2 helpers ----------------
#define FMA_X2(d, a, b, c) \
    asm("fma.rn.f32x2 %0, %1, %2, %3;" : "=l"(d) : "l"(a), "l"(b), "l"(c))
#define ADD_X2(d, a, b) \
    asm("add.rn.f32x2 %0, %1, %2;" : "=l"(d) : "l"(a), "l"(b))
#define DUP_X2(d, s) \
    asm("mov.b64 %0, {%1, %1};" : "=l"(d) : "r"(__float_as_uint(s)))
#define UNPACK_X2(lo, hi, p) \
    asm("mov.b64 {%0, %1}, %2;" : "=r"(lo), "=r"(hi) : "l"(p))

// ---------------- device scratch ----------------
__device__ float g_Gx[(size_t)TT * 3 * BB * HH];
__device__ float g_h[BB * HH];
__device__ float g_rh[BB * HH];
__device__ unsigned g_bcnt[NGRP];
__device__ unsigned g_bflag[NGRP];   // parity flag per group (0 initially; ends at 0)

// ---------------- split arrive/wait parity barrier (replay-safe) ----------------
__device__ __forceinline__ void bar_arrive(int grp, unsigned parity) {
    __syncthreads();                               // all warps' work done
    if (threadIdx.x == 0) {
        asm volatile("fence.acq_rel.gpu;" ::: "memory");   // publish CTA-mates' stores
        unsigned old;
        asm volatile("atom.acq_rel.gpu.global.add.u32 %0, [%1], %2;"
                     : "=r"(old) : "l"(&g_bcnt[grp]), "r"(1u));
        if (old == GC - 1u) {
            asm volatile("st.relaxed.gpu.global.u32 [%0], %1;"
                         :: "l"(&g_bcnt[grp]), "r"(0u));
            asm volatile("st.release.gpu.global.u32 [%0], %1;"
                         :: "l"(&g_bflag[grp]), "r"(parity));
        }
    }
}
__device__ __forceinline__ void bar_wait(int grp, unsigned parity) {
    if (threadIdx.x == 0) {
        unsigned cur;
        do {
            asm volatile("ld.acquire.gpu.global.u32 %0, [%1];"
                         : "=r"(cur) : "l"(&g_bflag[grp]));
        } while (cur != parity);
    }
    __syncthreads();
}

// =====================================================================================
// Phase 1: Gx[t][gate][b][j] = x[t,b,:] @ Wg[0:256,:] + bg   (unchanged from R5)
// =====================================================================================
__global__ void __launch_bounds__(256) phase1_gemm(
    const float* __restrict__ x,
    const float* __restrict__ Wz, const float* __restrict__ bz,
    const float* __restrict__ Wr, const float* __restrict__ br,
    const float* __restrict__ Wh, const float* __restrict__ bh)
{
    __shared__ float xs[32 * 132];
    __shared__ float ws[32 * 64];

    const int gate = blockIdx.y >> 3;
    const int jt0  = (blockIdx.y & 7) * 64;
    const float* W    = (gate == 0) ? Wz : ((gate == 1) ? Wr : Wh);
    const float* bias = (gate == 0) ? bz : ((gate == 1) ? br : bh);
    const int m0  = blockIdx.x * 128;
    const int tid = threadIdx.x;
    const int tn = tid & 15;
    const int tm = tid >> 4;

    unsigned long long pa[4][4];
#pragma unroll
    for (int i = 0; i < 4; i++)
#pragma unroll
        for (int j = 0; j < 4; j++) pa[i][j] = 0ull;

    for (int kc = 0; kc < 8; kc++) {
#pragma unroll
        for (int i = 0; i < 16; i++) {
            int idx = tid + i * 256;
            int row = idx >> 5, kk = idx & 31;
            xs[kk * 132 + row] = x[(size_t)(m0 + row) * DD + kc * 32 + kk];
        }
#pragma unroll
        for (int i = 0; i < 8; i++) {
            int idx = tid + i * 256;
            int kk = idx >> 6, jj = idx & 63;
            ws[kk * 64 + jj] = W[(size_t)(kc * 32 + kk) * HH + jt0 + jj];
        }
        __syncthreads();
#pragma unroll 8
        for (int kk = 0; kk < 32; kk++) {
            float4 w4 = *(const float4*)&ws[kk * 64 + tn * 4];
            ulonglong2 xL = *(const ulonglong2*)&xs[kk * 132 + tm * 8];
            ulonglong2 xH = *(const ulonglong2*)&xs[kk * 132 + tm * 8 + 4];
            unsigned long long hp[4] = {xL.x, xL.y, xH.x, xH.y};
            unsigned long long wd[4];
            DUP_X2(wd[0], w4.x); DUP_X2(wd[1], w4.y);
            DUP_X2(wd[2], w4.z); DUP_X2(wd[3], w4.w);
#pragma unroll
            for (int i = 0; i < 4; i++)
#pragma unroll
                for (int j = 0; j < 4; j++)
                    FMA_X2(pa[i][j], hp[i], wd[j], pa[i][j]);
        }
        __syncthreads();
    }

#pragma unroll
    for (int i = 0; i < 4; i++) {
#pragma unroll
        for (int j = 0; j < 4; j++) {
            unsigned lo, hi;
            UNPACK_X2(lo, hi, pa[i][j]);
            float bj = bias[jt0 + tn * 4 + j];
            int mA = m0 + tm * 8 + 2 * i;
            int tA = mA >> 6, bA = mA & 63;
            g_Gx[(((size_t)tA * 3 + gate) * BB + bA) * HH + jt0 + tn * 4 + j] =
                __uint_as_float(lo) + bj;
            int mB = mA + 1;
            int tB = mB >> 6, bB = mB & 63;
            g_Gx[(((size_t)tB * 3 + gate) * BB + bB) * HH + jt0 + tn * 4 + j] =
                __uint_as_float(hi) + bj;
        }
    }
}

// =====================================================================================
// Phase 2 helpers: per-stream stage1 / stage2 (column-pair packed f32x2 dots)
// Stage1 warp roles: khalf=w&1 (K/2), jt=(w>>1)&1 (16 cols), gate=w>>2 (0=z,1=r)
// Stage2 warp roles: jt=w&1 (16 cols), kq=w>>2.. (w>>1, K/4)
// After butterfly lane owns packed v=lane: b=lane>>3, colpair cp=lane&7,
// cols = jt*16 + 2cp + {0,1}.
// =====================================================================================
__device__ __forceinline__ void do_stage1(
    int t, int b0, int j0, const float* __restrict__ hsrc,
    const float* wzs, const float* wrs,
    float* hbuf, float* z_s, float* hc, unsigned long long* part)
{
    const int tid = threadIdx.x, warp = tid >> 5, lane = tid & 31;
    const int khalf = warp & 1, jt = (warp >> 1) & 1, gate = warp >> 2;
    const int b = lane >> 3, cp = lane & 7, col0 = jt * 16 + 2 * cp;

    // fill hbuf [512][4] with h
#pragma unroll
    for (int q = 0; q < 2; q++) {
        int k = tid + q * NT;
        float4 v;
        v.x = __ldcg(&hsrc[(size_t)(b0 + 0) * HH + k]);
        v.y = __ldcg(&hsrc[(size_t)(b0 + 1) * HH + k]);
        v.z = __ldcg(&hsrc[(size_t)(b0 + 2) * HH + k]);
        v.w = __ldcg(&hsrc[(size_t)(b0 + 3) * HH + k]);
        *(float4*)&hbuf[k * 4] = v;
    }
    __syncthreads();
    if (tid < 128) hc[tid] = hbuf[(j0 + (tid & 31)) * 4 + (tid >> 5)];

    // Gx prefetch (epilogue warps only)
    float gx0 = 0.f, gx1 = 0.f;
    if (khalf == 0) {
        size_t idx = (((size_t)t * 3 + gate) * BB + b0 + b) * HH + j0 + col0;
        float2 g = *(const float2*)&g_Gx[idx];
        gx0 = g.x; gx1 = g.y;
    }

    // dot over K=256 (this warp's half)
    unsigned long long a2[32];
#pragma unroll
    for (int v = 0; v < 32; v++) a2[v] = 0ull;
    {
        const float* wg = gate ? wrs : wzs;
        const int k0 = khalf * 256;
        const int s0 = (jt * 4 + 0) ^ (lane & 7), s1 = (jt * 4 + 1) ^ (lane & 7);
        const int s2 = (jt * 4 + 2) ^ (lane & 7), s3 = (jt * 4 + 3) ^ (lane & 7);
        const float4* wp = (const float4*)(wg + (k0 + lane) * JC);
        const float4* hp = (const float4*)(hbuf + (k0 + lane) * 4);
#pragma unroll
        for (int i = 0; i < 8; i++) {
            ulonglong2 wa = *(const ulonglong2*)(wp + s0);
            ulonglong2 wb = *(const ulonglong2*)(wp + s1);
            ulonglong2 wc = *(const ulonglong2*)(wp + s2);
            ulonglong2 we = *(const ulonglong2*)(wp + s3);
            float4 h4 = *(const float4*)hp;
            unsigned long long hd0, hd1, hd2, hd3;
            DUP_X2(hd0, h4.x); DUP_X2(hd1, h4.y);
            DUP_X2(hd2, h4.z); DUP_X2(hd3, h4.w);
            unsigned long long wpr[8] = {wa.x, wa.y, wb.x, wb.y, wc.x, wc.y, we.x, we.y};
#pragma unroll
            for (int c = 0; c < 8; c++) {
                FMA_X2(a2[0 * 8 + c], hd0, wpr[c], a2[0 * 8 + c]);
                FMA_X2(a2[1 * 8 + c], hd1, wpr[c], a2[1 * 8 + c]);
                FMA_X2(a2[2 * 8 + c], hd2, wpr[c], a2[2 * 8 + c]);
                FMA_X2(a2[3 * 8 + c], hd3, wpr[c], a2[3 * 8 + c]);
            }
            wp += 32 * JC / 4;
            hp += 32;
        }
    }
    // butterfly over 32 packed values -> lane owns v=lane
#pragma unroll
    for (int s = 0; s < 5; s++) {
        const int m = 16 >> s, half = 16 >> s;
        bool up = (lane & m) != 0;
#pragma unroll
        for (int i = 0; i < half; i++) {
            unsigned long long send = up ? a2[i] : a2[i + half];
            unsigned long long r = __shfl_xor_sync(0xffffffffu, send, m);
            unsigned long long keep = up ? a2[i + half] : a2[i];
            ADD_X2(a2[i], keep, r);
        }
    }
    // cross-khalf combine + epilogue
    if (khalf == 1) part[(gate * 2 + jt) * 32 + lane] = a2[0];
    __syncthreads();
    if (khalf == 0) {
        unsigned long long tot;
        ADD_X2(tot, a2[0], part[(gate * 2 + jt) * 32 + lane]);
        unsigned lo, hi;
        UNPACK_X2(lo, hi, tot);
        float p0 = __uint_as_float(lo) + gx0;
        float p1 = __uint_as_float(hi) + gx1;
        float sg0 = 1.f / (1.f + __expf(-p0));
        float sg1 = 1.f / (1.f + __expf(-p1));
        if (gate == 0) {
            z_s[b * 32 + col0]     = sg0;
            z_s[b * 32 + col0 + 1] = sg1;
        } else {
            float rh0 = sg0 * hbuf[(j0 + col0) * 4 + b];
            float rh1 = sg1 * hbuf[(j0 + col0 + 1) * 4 + b];
            asm volatile("st.global.cg.v2.f32 [%0], {%1, %2};"
                         :: "l"(&g_rh[(size_t)(b0 + b) * HH + j0 + col0]),
                            "f"(rh0), "f"(rh1) : "memory");
        }
    }
}

__device__ __forceinline__ void do_stage2(
    int t, int b0, int j0, const float* whs,
    float* hbuf, const float* z_s, const float* hc,
    unsigned long long* part, float* __restrict__ out)
{
    const int tid = threadIdx.x, warp = tid >> 5, lane = tid & 31;
    const int jt = warp & 1, kq = warp >> 1;
    const int b = lane >> 3, cp = lane & 7, col0 = jt * 16 + 2 * cp;

    // fill hbuf with r*h
#pragma unroll
    for (int q = 0; q < 2; q++) {
        int k = tid + q * NT;
        float4 v;
        v.x = __ldcg(&g_rh[(size_t)(b0 + 0) * HH + k]);
        v.y = __ldcg(&g_rh[(size_t)(b0 + 1) * HH + k]);
        v.z = __ldcg(&g_rh[(size_t)(b0 + 2) * HH + k]);
        v.w = __ldcg(&g_rh[(size_t)(b0 + 3) * HH + k]);
        *(float4*)&hbuf[k * 4] = v;
    }
    __syncthreads();

    float gx0 = 0.f, gx1 = 0.f;
    if (kq == 0) {
        size_t idx = (((size_t)t * 3 + 2) * BB + b0 + b) * HH + j0 + col0;
        float2 g = *(const float2*)&g_Gx[idx];
        gx0 = g.x; gx1 = g.y;
    }

    unsigned long long a2[32];
#pragma unroll
    for (int v = 0; v < 32; v++) a2[v] = 0ull;
    {
        const int k0 = kq * 128;
        const int s0 = (jt * 4 + 0) ^ (lane & 7), s1 = (jt * 4 + 1) ^ (lane & 7);
        const int s2 = (jt * 4 + 2) ^ (lane & 7), s3 = (jt * 4 + 3) ^ (lane & 7);
        const float4* wp = (const float4*)(whs + (k0 + lane) * JC);
        const float4* hp = (const float4*)(hbuf + (k0 + lane) * 4);
#pragma unroll
        for (int i = 0; i < 4; i++) {
            ulonglong2 wa = *(const ulonglong2*)(wp + s0);
            ulonglong2 wb = *(const ulonglong2*)(wp + s1);
            ulonglong2 wc = *(const ulonglong2*)(wp + s2);
            ulonglong2 we = *(const ulonglong2*)(wp + s3);
            float4 h4 = *(const float4*)hp;
            unsigned long long hd0, hd1, hd2, hd3;
            DUP_X2(hd0, h4.x); DUP_X2(hd1, h4.y);
            DUP_X2(hd2, h4.z); DUP_X2(hd3, h4.w);
            unsigned long long wpr[8] = {wa.x, wa.y, wb.x, wb.y, wc.x, wc.y, we.x, we.y};
#pragma unroll
            for (int c = 0; c < 8; c++) {
                FMA_X2(a2[0 * 8 + c], hd0, wpr[c], a2[0 * 8 + c]);
                FMA_X2(a2[1 * 8 + c], hd1, wpr[c], a2[1 * 8 + c]);
                FMA_X2(a2[2 * 8 + c], hd2, wpr[c], a2[2 * 8 + c]);
                FMA_X2(a2[3 * 8 + c], hd3, wpr[c], a2[3 * 8 + c]);
            }
            wp += 32 * JC / 4;
            hp += 32;
        }
    }
#pragma unroll
    for (int s = 0; s < 5; s++) {
        const int m = 16 >> s, half = 16 >> s;
        bool up = (lane & m) != 0;
#pragma unroll
        for (int i = 0; i < half; i++) {
            unsigned long long send = up ? a2[i] : a2[i + half];
            unsigned long long r = __shfl_xor_sync(0xffffffffu, send, m);
            unsigned long long keep = up ? a2[i + half] : a2[i];
            ADD_X2(a2[i], keep, r);
        }
    }
    if (kq > 0) part[((kq - 1) * 2 + jt) * 32 + lane] = a2[0];
    __syncthreads();
    if (kq == 0) {
        unsigned long long tot = a2[0];
        ADD_X2(tot, tot, part[(0 * 2 + jt) * 32 + lane]);
        ADD_X2(tot, tot, part[(1 * 2 + jt) * 32 + lane]);
        ADD_X2(tot, tot, part[(2 * 2 + jt) * 32 + lane]);
        unsigned lo, hi;
        UNPACK_X2(lo, hi, tot);
        float ht0 = tanhf(__uint_as_float(lo) + gx0);
        float ht1 = tanhf(__uint_as_float(hi) + gx1);
        float z0 = z_s[b * 32 + col0],     z1 = z_s[b * 32 + col0 + 1];
        float o0 = hc[b * 32 + col0],      o1 = hc[b * 32 + col0 + 1];
        float hn0 = o0 + z0 * (ht0 - o0);
        float hn1 = o1 + z1 * (ht1 - o1);
        asm volatile("st.global.cg.v2.f32 [%0], {%1, %2};"
                     :: "l"(&g_h[(size_t)(b0 + b) * HH + j0 + col0]),
                        "f"(hn0), "f"(hn1) : "memory");
        asm volatile("st.global.cg.v2.f32 [%0], {%1, %2};"
                     :: "l"(&out[((size_t)t * BB + b0 + b) * HH + j0 + col0]),
                        "f"(hn0), "f"(hn1) : "memory");
    }
}

// =====================================================================================
// Phase 2: dual-stream persistent GRU. 128 CTAs; CTA (gpair, rank) serves groups
// gA=2*gpair (batch 8gpair..+3) and gB=2*gpair+1 (+4..+7), columns [32*rank, +32).
// Barrier latency of each stream hidden under the other stream's fill+dot.
// =====================================================================================
__global__ void __launch_bounds__(NT, 1) phase2_gru(
    const float* __restrict__ h0in,
    const float* __restrict__ Wz,
    const float* __restrict__ Wr,
    const float* __restrict__ Wh,
    float* __restrict__ out)
{
    extern __shared__ float sm[];
    float* wzs   = sm;                       // [512][32] swizzled
    float* wrs   = wzs + HH * JC;
    float* whs   = wrs + HH * JC;
    float* hbufA = whs + HH * JC;            // [512][4]
    float* hbufB = hbufA + HH * 4;
    float* z_sA  = hbufB + HH * 4;           // [4][32]
    float* z_sB  = z_sA + 128;
    float* hcA   = z_sB + 128;               // [4][32]
    float* hcB   = hcA + 128;
    unsigned long long* partA = (unsigned long long*)(hcB + 128);   // [6][32]
    unsigned long long* partB = partA + 6 * 32;

    const int rank  = blockIdx.x & 15;
    const int gpair = blockIdx.x >> 4;
    const int gA = gpair * 2, gB = gpair * 2 + 1;
    const int b0A = gpair * 8, b0B = gpair * 8 + 4;
    const int j0 = rank * JC;
    const int tid = threadIdx.x;

    // resident recurrent weights (rows DD..DD+511), float4-slot XOR swizzle
    for (int idx = tid; idx < HH * JC; idx += NT) {
        int k = idx >> 5, jl = idx & 31;
        int phys = k * JC + ((((jl >> 2) ^ (k & 7))) << 2) + (jl & 3);
        size_t goff = (size_t)(DD + k) * HH + j0 + jl;
        wzs[phys] = Wz[goff];
        wrs[phys] = Wr[goff];
        whs[phys] = Wh[goff];
    }
    __syncthreads();

    for (int t = 0; t < TT; t++) {
        const float* hsrc = (t == 0) ? h0in : (const float*)g_h;

        // ----- stream A stage 1 -----
        if (t > 0) bar_wait(gA, 0u);
        do_stage1(t, b0A, j0, hsrc, wzs, wrs, hbufA, z_sA, hcA, partA);
        bar_arrive(gA, 1u);

        // ----- stream B stage 1 (hides A's barrier) -----
        if (t > 0) bar_wait(gB, 0u);
        do_stage1(t, b0B, j0, hsrc, wzs, wrs, hbufB, z_sB, hcB, partB);
        bar_arrive(gB, 1u);

        // ----- stream A stage 2 -----
        bar_wait(gA, 1u);
        do_stage2(t, b0A, j0, whs, hbufA, z_sA, hcA, partA, out);
        bar_arrive(gA, 0u);

        // ----- stream B stage 2 (hides A's end barrier) -----
        bar_wait(gB, 1u);
        do_stage2(t, b0B, j0, whs, hbufB, z_sB, hcB, partB, out);
        bar_arrive(gB, 0u);
    }
}

// =====================================================================================
extern "C" void kernel_launch(void* const* d_in, const int* in_sizes, int n_in,
                              void* d_out, int out_size)
{
    const float* x  = (const float*)d_in[0];
    const float* h0 = (const float*)d_in[1];
    const float* Wz = (const float*)d_in[2];
    const float* bz = (const float*)d_in[3];
    const float* Wr = (const float*)d_in[4];
    const float* br = (const float*)d_in[5];
    const float* Wh = (const float*)d_in[6];
    const float* bh = (const float*)d_in[7];
    float* out = (float*)d_out;

    const int smem_bytes = (3 * HH * JC + 2 * HH * 4 + 4 * 128) * (int)sizeof(float)
                         + 2 * 6 * 32 * (int)sizeof(unsigned long long);
    cudaFuncSetAttribute(phase2_gru, cudaFuncAttributeMaxDynamicSharedMemorySize, smem_bytes);

    dim3 g1((TT * BB) / 128, 24);
    phase1_gemm<<<g1, 256>>>(x, Wz, bz, Wr, br, Wh, bh);

    phase2_gru<<<NGRP * GC / 2, NT, smem_bytes>>>(h0, Wz, Wr, Wh, out);
}

// round 8
// speedup vs baseline: 1.5064x; 1.5064x over previous
#include <cuda_runtime.h>
#include <math.h>

#define TT 2048
#define BB 64
#define DD 256
#define HH 512

#define NGROUPS 8
#define GC 16         // CTAs per group
#define GB 8          // batch elems per group
#define JC 32         // output columns owned per CTA
#define NT 512        // threads per CTA (16 warps -> 4 warps/SMSP)
#define HPAD 12       // hbuf row pad: 12 floats (16B-aligned rows, conflict-free LDS.128)

// ---------------- packed fp32x2 helpers ----------------
#define FMA_X2(d, a, b, c) \
    asm("fma.rn.f32x2 %0, %1, %2, %3;" : "=l"(d) : "l"(a), "l"(b), "l"(c))
#define ADD_X2(d, a, b) \
    asm("add.rn.f32x2 %0, %1, %2;" : "=l"(d) : "l"(a), "l"(b))
#define DUP_X2(d, s) \
    asm("mov.b64 %0, {%1, %1};" : "=l"(d) : "r"(__float_as_uint(s)))
#define UNPACK_X2(lo, hi, p) \
    asm("mov.b64 {%0, %1}, %2;" : "=r"(lo), "=r"(hi) : "l"(p))

// ---------------- device scratch ----------------
__device__ float g_Gx[(size_t)TT * 3 * BB * HH];
__device__ float g_h[BB * HH];
__device__ float g_rh[BB * HH];
__device__ unsigned g_bcnt[NGROUPS];
__device__ unsigned g_bgen[NGROUPS];

// ---------------- group barrier (R5-proven: acq/rel atomics, gen-based) -------------
__device__ __forceinline__ void group_barrier(int grp) {
    __syncthreads();
    if (threadIdx.x == 0) {
        unsigned gen;
        asm volatile("ld.acquire.gpu.global.u32 %0, [%1];"
                     : "=r"(gen) : "l"(&g_bgen[grp]));
        unsigned old;
        asm volatile("atom.acq_rel.gpu.global.add.u32 %0, [%1], %2;"
                     : "=r"(old) : "l"(&g_bcnt[grp]), "r"(1u));
        if (old == GC - 1u) {
            asm volatile("st.relaxed.gpu.global.u32 [%0], %1;"
                         :: "l"(&g_bcnt[grp]), "r"(0u));
            asm volatile("st.release.gpu.global.u32 [%0], %1;"
                         :: "l"(&g_bgen[grp]), "r"(gen + 1u));
        } else {
            unsigned cur;
            do {
                asm volatile("ld.acquire.gpu.global.u32 %0, [%1];"
                             : "=r"(cur) : "l"(&g_bgen[grp]));
            } while (cur == gen);
        }
    }
    __syncthreads();
}

// =====================================================================================
// Phase 1: Gx[t][gate][b][j] = x[t,b,:] @ Wg[0:256,:] + bg   (unchanged, R5-proven)
// =====================================================================================
__global__ void __launch_bounds__(256) phase1_gemm(
    const float* __restrict__ x,
    const float* __restrict__ Wz, const float* __restrict__ bz,
    const float* __restrict__ Wr, const float* __restrict__ br,
    const float* __restrict__ Wh, const float* __restrict__ bh)
{
    __shared__ float xs[32 * 132];
    __shared__ float ws[32 * 64];

    const int gate = blockIdx.y >> 3;
    const int jt0  = (blockIdx.y & 7) * 64;
    const float* W    = (gate == 0) ? Wz : ((gate == 1) ? Wr : Wh);
    const float* bias = (gate == 0) ? bz : ((gate == 1) ? br : bh);
    const int m0  = blockIdx.x * 128;
    const int tid = threadIdx.x;
    const int tn = tid & 15;
    const int tm = tid >> 4;

    unsigned long long pa[4][4];
#pragma unroll
    for (int i = 0; i < 4; i++)
#pragma unroll
        for (int j = 0; j < 4; j++) pa[i][j] = 0ull;

    for (int kc = 0; kc < 8; kc++) {
#pragma unroll
        for (int i = 0; i < 16; i++) {
            int idx = tid + i * 256;
            int row = idx >> 5, kk = idx & 31;
            xs[kk * 132 + row] = x[(size_t)(m0 + row) * DD + kc * 32 + kk];
        }
#pragma unroll
        for (int i = 0; i < 8; i++) {
            int idx = tid + i * 256;
            int kk = idx >> 6, jj = idx & 63;
            ws[kk * 64 + jj] = W[(size_t)(kc * 32 + kk) * HH + jt0 + jj];
        }
        __syncthreads();
#pragma unroll 8
        for (int kk = 0; kk < 32; kk++) {
            float4 w4 = *(const float4*)&ws[kk * 64 + tn * 4];
            ulonglong2 xL = *(const ulonglong2*)&xs[kk * 132 + tm * 8];
            ulonglong2 xH = *(const ulonglong2*)&xs[kk * 132 + tm * 8 + 4];
            unsigned long long hp[4] = {xL.x, xL.y, xH.x, xH.y};
            unsigned long long wd[4];
            DUP_X2(wd[0], w4.x); DUP_X2(wd[1], w4.y);
            DUP_X2(wd[2], w4.z); DUP_X2(wd[3], w4.w);
#pragma unroll
            for (int i = 0; i < 4; i++)
#pragma unroll
                for (int j = 0; j < 4; j++)
                    FMA_X2(pa[i][j], hp[i], wd[j], pa[i][j]);
        }
        __syncthreads();
    }

#pragma unroll
    for (int i = 0; i < 4; i++) {
#pragma unroll
        for (int j = 0; j < 4; j++) {
            unsigned lo, hi;
            UNPACK_X2(lo, hi, pa[i][j]);
            float bj = bias[jt0 + tn * 4 + j];
            int mA = m0 + tm * 8 + 2 * i;
            int tA = mA >> 6, bA = mA & 63;
            g_Gx[(((size_t)tA * 3 + gate) * BB + bA) * HH + jt0 + tn * 4 + j] =
                __uint_as_float(lo) + bj;
            int mB = mA + 1;
            int tB = mB >> 6, bB = mB & 63;
            g_Gx[(((size_t)tB * 3 + gate) * BB + bB) * HH + jt0 + tn * 4 + j] =
                __uint_as_float(hi) + bj;
        }
    }
}

// =====================================================================================
// Phase 2: persistent GRU, single-stream, NT=512 (16 warps).
// Stage1: warp w -> gate=w>>3 (0=z,1=r), jt=w&7 (4 cols), full K=512.
// Stage2: warp w -> khalf=w>>3 (K/2),    jt=w&7 (4 cols), + smem combine.
// 16 packed accumulators. Reduction = 1 non-splitting butterfly (m=16) +
// 4 splitting stages (m=8,4,2,1) -> lanes<16 own v=lane&15.
// =====================================================================================
__global__ void __launch_bounds__(NT, 1) phase2_gru(
    const float* __restrict__ h0in,
    const float* __restrict__ Wz,
    const float* __restrict__ Wr,
    const float* __restrict__ Wh,
    float* __restrict__ out)
{
    extern __shared__ float sm[];
    float* wzs  = sm;                     // [512][32] swizzled
    float* wrs  = wzs + HH * JC;
    float* whs  = wrs + HH * JC;
    float* hbuf = whs + HH * JC;          // [512][HPAD]
    float* z_s  = hbuf + HH * HPAD;       // [8][32]
    float* ho_s = z_s + GB * JC;          // [8][32]
    unsigned long long* partU = (unsigned long long*)(ho_s + GB * JC);  // [8][16]

    const int grp  = blockIdx.x >> 4;
    const int rank = blockIdx.x & 15;
    const int b0 = grp * GB;
    const int j0 = rank * JC;
    const int tid  = threadIdx.x;
    const int warp = tid >> 5;
    const int lane = tid & 31;

    // resident recurrent weights (rows DD..DD+511), float4-slot XOR swizzle
    for (int idx = tid; idx < HH * JC; idx += NT) {
        int k = idx >> 5, jl = idx & 31;
        int phys = k * JC + ((((jl >> 2) ^ (k & 7))) << 2) + (jl & 3);
        size_t goff = (size_t)(DD + k) * HH + j0 + jl;
        wzs[phys] = Wz[goff];
        wrs[phys] = Wr[goff];
        whs[phys] = Wh[goff];
    }
    __syncthreads();

    const int gate1 = warp >> 3;            // stage1: 0=z, 1=r
    const int jt    = warp & 7;             // 4-col tile (both stages)
    const int khalf = warp >> 3;            // stage2 k-half
    const int slotW = jt ^ (lane & 7);      // swizzled float4 slot (k&7 == lane&7)
    const int lan15 = lane & 15;
    const int p     = lan15 >> 2;           // owned b-pair (bA=2p, bB=2p+1)
    const int col   = jt * 4 + (lan15 & 3); // owned column within [0,32)
    const bool epi  = (lane < 16);

    for (int t = 0; t < TT; t++) {
        // ---------------- fill hbuf with h: one k-row per thread ----------------
        const float* hsrc = (t == 0) ? h0in : (const float*)g_h;
        {
            int k = tid;
            float v0 = __ldcg(&hsrc[(size_t)(b0 + 0) * HH + k]);
            float v1 = __ldcg(&hsrc[(size_t)(b0 + 1) * HH + k]);
            float v2 = __ldcg(&hsrc[(size_t)(b0 + 2) * HH + k]);
            float v3 = __ldcg(&hsrc[(size_t)(b0 + 3) * HH + k]);
            float v4 = __ldcg(&hsrc[(size_t)(b0 + 4) * HH + k]);
            float v5 = __ldcg(&hsrc[(size_t)(b0 + 5) * HH + k]);
            float v6 = __ldcg(&hsrc[(size_t)(b0 + 6) * HH + k]);
            float v7 = __ldcg(&hsrc[(size_t)(b0 + 7) * HH + k]);
            float4* row = (float4*)&hbuf[k * HPAD];
            row[0] = make_float4(v0, v1, v2, v3);
            row[1] = make_float4(v4, v5, v6, v7);
        }
        __syncthreads();

        // stash h_old for own columns (stage-2 update reads after hbuf reuse)
        if (tid < 256) {
            int b = tid >> 5, jl = tid & 31;
            ho_s[tid] = hbuf[(j0 + jl) * HPAD + b];
        }

        // prefetch Gx (epilogue lanes only)
        float gx1lo = 0.f, gx1hi = 0.f, gx2lo = 0.f, gx2hi = 0.f;
        if (epi) {
            size_t r1 = (((size_t)t * 3 + gate1) * BB + b0 + 2 * p) * HH + j0 + col;
            gx1lo = __ldg(&g_Gx[r1]);
            gx1hi = __ldg(&g_Gx[r1 + HH]);
        }
        if (epi && khalf == 0) {
            size_t r2 = (((size_t)t * 3 + 2) * BB + b0 + 2 * p) * HH + j0 + col;
            gx2lo = __ldg(&g_Gx[r2]);
            gx2hi = __ldg(&g_Gx[r2 + HH]);
        }

        // ================= stage 1 dot (full K=512 per warp) =================
        unsigned long long a2[16];
#pragma unroll
        for (int v = 0; v < 16; v++) a2[v] = 0ull;
        {
            const float4* wp = (const float4*)((gate1 ? wrs : wzs) + lane * JC);
            const char*   hp = (const char*)(hbuf + lane * HPAD);
#pragma unroll
            for (int i = 0; i < 16; i++) {
                float4 w4 = wp[slotW];
                ulonglong2 hL = *(const ulonglong2*)hp;
                ulonglong2 hH = *(const ulonglong2*)(hp + 16);
                unsigned long long hb[4] = {hL.x, hL.y, hH.x, hH.y};
                unsigned long long wd[4];
                DUP_X2(wd[0], w4.x); DUP_X2(wd[1], w4.y);
                DUP_X2(wd[2], w4.z); DUP_X2(wd[3], w4.w);
#pragma unroll
                for (int q = 0; q < 4; q++)
#pragma unroll
                    for (int c = 0; c < 4; c++)
                        FMA_X2(a2[q * 4 + c], hb[q], wd[c], a2[q * 4 + c]);
                wp += 32 * JC / 4;
                hp += 32 * HPAD * 4;
            }
        }
        // --- reduction: pre-stage m=16 (non-splitting), then 4 splitting stages ---
#pragma unroll
        for (int i = 0; i < 16; i++) {
            unsigned long long r = __shfl_xor_sync(0xffffffffu, a2[i], 16);
            ADD_X2(a2[i], a2[i], r);
        }
#pragma unroll
        for (int s = 0; s < 4; s++) {
            const int m = 8 >> s, half = 8 >> s;
            bool up = (lane & m) != 0;
#pragma unroll
            for (int i = 0; i < half; i++) {
                unsigned long long send = up ? a2[i] : a2[i + half];
                unsigned long long r = __shfl_xor_sync(0xffffffffu, send, m);
                unsigned long long keep = up ? a2[i + half] : a2[i];
                ADD_X2(a2[i], keep, r);
            }
        }
        if (epi) {
            unsigned lo, hi;
            UNPACK_X2(lo, hi, a2[0]);
            float pre0 = __uint_as_float(lo) + gx1lo;
            float pre1 = __uint_as_float(hi) + gx1hi;
            float s0 = 1.f / (1.f + __expf(-pre0));
            float s1 = 1.f / (1.f + __expf(-pre1));
            int bA = 2 * p, bB = 2 * p + 1;
            if (gate1 == 0) {
                z_s[bA * JC + col] = s0;
                z_s[bB * JC + col] = s1;
            } else {
                float rh0 = s0 * hbuf[(j0 + col) * HPAD + bA];
                float rh1 = s1 * hbuf[(j0 + col) * HPAD + bB];
                __stcg(&g_rh[(size_t)(b0 + bA) * HH + j0 + col], rh0);
                __stcg(&g_rh[(size_t)(b0 + bB) * HH + j0 + col], rh1);
            }
        }

        group_barrier(grp);   // g_rh complete group-wide

        // ================= stage 2: fill hbuf with r*h =================
        {
            int k = tid;
            float v0 = __ldcg(&g_rh[(size_t)(b0 + 0) * HH + k]);
            float v1 = __ldcg(&g_rh[(size_t)(b0 + 1) * HH + k]);
            float v2 = __ldcg(&g_rh[(size_t)(b0 + 2) * HH + k]);
            float v3 = __ldcg(&g_rh[(size_t)(b0 + 3) * HH + k]);
            float v4 = __ldcg(&g_rh[(size_t)(b0 + 4) * HH + k]);
            float v5 = __ldcg(&g_rh[(size_t)(b0 + 5) * HH + k]);
            float v6 = __ldcg(&g_rh[(size_t)(b0 + 6) * HH + k]);
            float v7 = __ldcg(&g_rh[(size_t)(b0 + 7) * HH + k]);
            float4* row = (float4*)&hbuf[k * HPAD];
            row[0] = make_float4(v0, v1, v2, v3);
            row[1] = make_float4(v4, v5, v6, v7);
        }
        __syncthreads();

        // stage-2 dot (K/2 per warp)
#pragma unroll
        for (int v = 0; v < 16; v++) a2[v] = 0ull;
        {
            const int k0 = khalf * 256 + lane;
            const float4* wp = (const float4*)(whs + k0 * JC);
            const char*   hp = (const char*)(hbuf + k0 * HPAD);
#pragma unroll
            for (int i = 0; i < 8; i++) {
                float4 w4 = wp[slotW];
                ulonglong2 hL = *(const ulonglong2*)hp;
                ulonglong2 hH = *(const ulonglong2*)(hp + 16);
                unsigned long long hb[4] = {hL.x, hL.y, hH.x, hH.y};
                unsigned long long wd[4];
                DUP_X2(wd[0], w4.x); DUP_X2(wd[1], w4.y);
                DUP_X2(wd[2], w4.z); DUP_X2(wd[3], w4.w);
#pragma unroll
                for (int q = 0; q < 4; q++)
#pragma unroll
                    for (int c = 0; c < 4; c++)
                        FMA_X2(a2[q * 4 + c], hb[q], wd[c], a2[q * 4 + c]);
                wp += 32 * JC / 4;
                hp += 32 * HPAD * 4;
            }
        }
#pragma unroll
        for (int i = 0; i < 16; i++) {
            unsigned long long r = __shfl_xor_sync(0xffffffffu, a2[i], 16);
            ADD_X2(a2[i], a2[i], r);
        }
#pragma unroll
        for (int s = 0; s < 4; s++) {
            const int m = 8 >> s, half = 8 >> s;
            bool up = (lane & m) != 0;
#pragma unroll
            for (int i = 0; i < half; i++) {
                unsigned long long send = up ? a2[i] : a2[i + half];
                unsigned long long r = __shfl_xor_sync(0xffffffffu, send, m);
                unsigned long long keep = up ? a2[i + half] : a2[i];
                ADD_X2(a2[i], keep, r);
            }
        }
        // cross-khalf combine + update epilogue
        if (khalf == 1 && epi) partU[jt * 16 + lan15] = a2[0];
        __syncthreads();
        if (khalf == 0 && epi) {
            unsigned long long tot;
            ADD_X2(tot, a2[0], partU[jt * 16 + lan15]);
            unsigned lo, hi;
            UNPACK_X2(lo, hi, tot);
            int bA = 2 * p, bB = 2 * p + 1;
            float ht0 = tanhf(__uint_as_float(lo) + gx2lo);
            float ht1 = tanhf(__uint_as_float(hi) + gx2hi);
            float z0 = z_s[bA * JC + col], z1 = z_s[bB * JC + col];
            float o0 = ho_s[bA * JC + col], o1 = ho_s[bB * JC + col];
            float hn0 = o0 + z0 * (ht0 - o0);
            float hn1 = o1 + z1 * (ht1 - o1);
            __stcg(&g_h[(size_t)(b0 + bA) * HH + j0 + col], hn0);
            __stcg(&g_h[(size_t)(b0 + bB) * HH + j0 + col], hn1);
            out[((size_t)t * BB + b0 + bA) * HH + j0 + col] = hn0;
            out[((size_t)t * BB + b0 + bB) * HH + j0 + col] = hn1;
        }

        group_barrier(grp);   // g_h complete before next step
    }
}

// =====================================================================================
extern "C" void kernel_launch(void* const* d_in, const int* in_sizes, int n_in,
                              void* d_out, int out_size)
{
    const float* x  = (const float*)d_in[0];
    const float* h0 = (const float*)d_in[1];
    const float* Wz = (const float*)d_in[2];
    const float* bz = (const float*)d_in[3];
    const float* Wr = (const float*)d_in[4];
    const float* br = (const float*)d_in[5];
    const float* Wh = (const float*)d_in[6];
    const float* bh = (const float*)d_in[7];
    float* out = (float*)d_out;

    const int smem_bytes = (3 * HH * JC + HH * HPAD + 2 * GB * JC) * (int)sizeof(float)
                         + 8 * 16 * (int)sizeof(unsigned long long);
    cudaFuncSetAttribute(phase2_gru, cudaFuncAttributeMaxDynamicSharedMemorySize, smem_bytes);

    dim3 g1((TT * BB) / 128, 24);
    phase1_gemm<<<g1, 256>>>(x, Wz, bz, Wr, br, Wh, bh);

    phase2_gru<<<NGROUPS * GC, NT, smem_bytes>>>(h0, Wz, Wr, Wh, out);
}